// round 1
// baseline (speedup 1.0000x reference)
#include <cuda_runtime.h>
#include <math.h>
#include <float.h>

#define Bb_ 2
#define Ss_ 2048
#define Dd_ 1024
#define Hh_ 16
#define HD_ 64
#define Mm_ (Bb_*Ss_)      /* 4096 */
#define NQKV_ (3*Dd_)      /* 3072 */

// Scratch (allocation-free rule: __device__ globals)
__device__ float g_Q[Bb_*Hh_*Ss_*HD_];   // [b,h,s,hd]
__device__ float g_K[Bb_*Hh_*Ss_*HD_];
__device__ float g_V[Bb_*Hh_*Ss_*HD_];
__device__ float g_AO[Mm_*Dd_];          // attention output [b,s,d]

// ---------------------------------------------------------------------------
// Kernel 1: QKV = x @ W_qkv + b_qkv, scatter to Q/K/V in [b,h,s,hd] layout
// BM=BN=128, BK=8, 256 threads, 8x8 per-thread tile
// ---------------------------------------------------------------------------
__global__ __launch_bounds__(256) void qkv_gemm_kernel(
    const float* __restrict__ A,      // x [4096,1024]
    const float* __restrict__ Wq,     // [1024,3072]
    const float* __restrict__ bq)     // [3072]
{
    __shared__ float As[8][128];
    __shared__ float Bs[8][128];
    const int K = Dd_, N = NQKV_;
    const int tid  = threadIdx.x;
    const int cRow = blockIdx.y, cCol = blockIdx.x;
    const int tr = tid >> 4, tc = tid & 15;
    const int rowA = tid >> 1, colA = (tid & 1) * 4;
    const int rowB = tid >> 5, colB = (tid & 31) * 4;

    const float* Ab = A  + (size_t)cRow * 128 * K;
    const float* Bbp = Wq + (size_t)cCol * 128;

    float acc[8][8];
    #pragma unroll
    for (int i = 0; i < 8; i++)
        #pragma unroll
        for (int j = 0; j < 8; j++) acc[i][j] = 0.f;

    for (int k0 = 0; k0 < K; k0 += 8) {
        float4 a = *(const float4*)&Ab[(size_t)rowA * K + k0 + colA];
        As[colA+0][rowA] = a.x;
        As[colA+1][rowA] = a.y;
        As[colA+2][rowA] = a.z;
        As[colA+3][rowA] = a.w;
        *(float4*)&Bs[rowB][colB] =
            *(const float4*)&Bbp[(size_t)(k0 + rowB) * N + colB];
        __syncthreads();

        #pragma unroll
        for (int k = 0; k < 8; k++) {
            float rm[8], rn[8];
            *(float4*)&rm[0] = *(float4*)&As[k][tr*8];
            *(float4*)&rm[4] = *(float4*)&As[k][tr*8+4];
            *(float4*)&rn[0] = *(float4*)&Bs[k][tc*8];
            *(float4*)&rn[4] = *(float4*)&Bs[k][tc*8+4];
            #pragma unroll
            for (int i = 0; i < 8; i++)
                #pragma unroll
                for (int j = 0; j < 8; j++)
                    acc[i][j] = fmaf(rm[i], rn[j], acc[i][j]);
        }
        __syncthreads();
    }

    // epilogue: bias + scatter to Q/K/V
    #pragma unroll
    for (int j = 0; j < 8; j++) {
        const int n = cCol*128 + tc*8 + j;
        const float bias = bq[n];
        const int h = n / 192;          // 3*HD = 192 per head
        const int c = n - h * 192;
        #pragma unroll
        for (int i = 0; i < 8; i++) {
            const int m = cRow*128 + tr*8 + i;
            const int b = m >> 11;              // / 2048
            const int s = m & (Ss_ - 1);
            const float v = acc[i][j] + bias;
            const size_t base = ((size_t)(b*Hh_ + h) * Ss_ + s) * HD_;
            if (c < 64)        g_Q[base + c]        = v;
            else if (c < 128)  g_K[base + c - 64]   = v;
            else               g_V[base + c - 128]  = v;
        }
    }
}

// ---------------------------------------------------------------------------
// Kernel 2: causal flash attention. One block per (bh, 64-row q tile).
// 256 threads, 4x4 per-thread S/O micro-tiles, online softmax.
// ---------------------------------------------------------------------------
#define ATTN_SMEM ((4096*3 + 64*68) * 4)   /* Qts,Kts,Vs (64x64) + Pts (64x68) */

__global__ __launch_bounds__(256) void attn_kernel()
{
    extern __shared__ float sm[];
    float* Qts = sm;                 // [d][r] transposed, pre-scaled
    float* Kts = sm + 4096;          // [d][c] transposed
    float* Vs  = sm + 8192;          // [c][d]
    float* Pts = sm + 12288;         // [c][r], row stride 68

    const int tid = threadIdx.x;
    const int qt  = blockIdx.x;      // 0..31
    const int bh  = blockIdx.y;      // 0..31
    const int tr = tid >> 4, tc = tid & 15;
    const int lr = tid >> 2;                 // loader row 0..63
    const int ld0 = (tid & 3) << 4;          // loader d base 0/16/32/48

    // load Q tile transposed, scaled by 1/sqrt(64)
    const float* Qg = g_Q + ((size_t)bh * Ss_ + qt*64) * HD_;
    #pragma unroll
    for (int q4 = 0; q4 < 4; q4++) {
        const int d = ld0 + q4*4;
        float4 v = *(const float4*)&Qg[lr*64 + d];
        Qts[(d+0)*64 + lr] = v.x * 0.125f;
        Qts[(d+1)*64 + lr] = v.y * 0.125f;
        Qts[(d+2)*64 + lr] = v.z * 0.125f;
        Qts[(d+3)*64 + lr] = v.w * 0.125f;
    }

    float mrow[4], lrow[4], O[4][4];
    #pragma unroll
    for (int i = 0; i < 4; i++) {
        mrow[i] = -INFINITY; lrow[i] = 0.f;
        #pragma unroll
        for (int j = 0; j < 4; j++) O[i][j] = 0.f;
    }

    for (int kt = 0; kt <= qt; kt++) {
        __syncthreads();   // Q stored (iter 0) / prev PV reads done
        const float* Kg = g_K + ((size_t)bh * Ss_ + kt*64) * HD_;
        const float* Vg = g_V + ((size_t)bh * Ss_ + kt*64) * HD_;
        #pragma unroll
        for (int q4 = 0; q4 < 4; q4++) {
            const int d = ld0 + q4*4;
            float4 kv = *(const float4*)&Kg[lr*64 + d];
            Kts[(d+0)*64 + lr] = kv.x;
            Kts[(d+1)*64 + lr] = kv.y;
            Kts[(d+2)*64 + lr] = kv.z;
            Kts[(d+3)*64 + lr] = kv.w;
            *(float4*)&Vs[lr*64 + d] = *(const float4*)&Vg[lr*64 + d];
        }
        __syncthreads();

        // S = Qs @ Ks^T (scaled)
        float sacc[4][4];
        #pragma unroll
        for (int i = 0; i < 4; i++)
            #pragma unroll
            for (int j = 0; j < 4; j++) sacc[i][j] = 0.f;
        #pragma unroll 8
        for (int d = 0; d < 64; d++) {
            float4 qv = *(float4*)&Qts[d*64 + tr*4];
            float4 kv = *(float4*)&Kts[d*64 + tc*4];
            float q[4] = {qv.x, qv.y, qv.z, qv.w};
            float k[4] = {kv.x, kv.y, kv.z, kv.w};
            #pragma unroll
            for (int i = 0; i < 4; i++)
                #pragma unroll
                for (int j = 0; j < 4; j++)
                    sacc[i][j] = fmaf(q[i], k[j], sacc[i][j]);
        }

        if (kt == qt) {   // causal mask inside diagonal tile
            #pragma unroll
            for (int i = 0; i < 4; i++)
                #pragma unroll
                for (int j = 0; j < 4; j++)
                    if (tc*4 + j > tr*4 + i) sacc[i][j] = -INFINITY;
        }

        // online softmax per row (16 lanes per row group = half warp)
        #pragma unroll
        for (int i = 0; i < 4; i++) {
            float mx = fmaxf(fmaxf(sacc[i][0], sacc[i][1]),
                             fmaxf(sacc[i][2], sacc[i][3]));
            #pragma unroll
            for (int off = 8; off >= 1; off >>= 1)
                mx = fmaxf(mx, __shfl_xor_sync(0xffffffffu, mx, off, 16));
            mx = fmaxf(mx, mrow[i]);
            const float alpha = __expf(mrow[i] - mx);
            mrow[i] = mx;
            float rs = 0.f;
            #pragma unroll
            for (int j = 0; j < 4; j++) {
                const float p = __expf(sacc[i][j] - mx);
                sacc[i][j] = p;
                rs += p;
            }
            #pragma unroll
            for (int off = 8; off >= 1; off >>= 1)
                rs += __shfl_xor_sync(0xffffffffu, rs, off, 16);
            lrow[i] = lrow[i] * alpha + rs;
            #pragma unroll
            for (int j = 0; j < 4; j++) O[i][j] *= alpha;
        }

        // stage P transposed
        #pragma unroll
        for (int i = 0; i < 4; i++)
            #pragma unroll
            for (int j = 0; j < 4; j++)
                Pts[(tc*4 + j)*68 + tr*4 + i] = sacc[i][j];
        __syncthreads();

        // O += P @ V
        #pragma unroll 8
        for (int c = 0; c < 64; c++) {
            float4 pv = *(float4*)&Pts[c*68 + tr*4];
            float4 vv = *(float4*)&Vs[c*64 + tc*4];
            float p[4] = {pv.x, pv.y, pv.z, pv.w};
            float v[4] = {vv.x, vv.y, vv.z, vv.w};
            #pragma unroll
            for (int i = 0; i < 4; i++)
                #pragma unroll
                for (int j = 0; j < 4; j++)
                    O[i][j] = fmaf(p[i], v[j], O[i][j]);
        }
    }

    // write out: [b,s,d] with d = h*64 + n
    const int b = bh / Hh_, h = bh - b*Hh_;
    #pragma unroll
    for (int i = 0; i < 4; i++) {
        const float inv = 1.0f / lrow[i];
        const size_t row = (size_t)(b*Ss_ + qt*64 + tr*4 + i) * Dd_ + h*64 + tc*4;
        float4 o = make_float4(O[i][0]*inv, O[i][1]*inv, O[i][2]*inv, O[i][3]*inv);
        *(float4*)&g_AO[row] = o;
    }
}

// ---------------------------------------------------------------------------
// Kernel 3: out = AO @ W_out + b_out
// ---------------------------------------------------------------------------
__global__ __launch_bounds__(256) void out_gemm_kernel(
    const float* __restrict__ Wo,     // [1024,1024]
    const float* __restrict__ bo,     // [1024]
    float* __restrict__ out)          // [4096,1024]
{
    __shared__ float As[8][128];
    __shared__ float Bs[8][128];
    const int K = Dd_, N = Dd_;
    const int tid  = threadIdx.x;
    const int cRow = blockIdx.y, cCol = blockIdx.x;
    const int tr = tid >> 4, tc = tid & 15;
    const int rowA = tid >> 1, colA = (tid & 1) * 4;
    const int rowB = tid >> 5, colB = (tid & 31) * 4;

    const float* Ab = g_AO + (size_t)cRow * 128 * K;
    const float* Bbp = Wo + (size_t)cCol * 128;

    float acc[8][8];
    #pragma unroll
    for (int i = 0; i < 8; i++)
        #pragma unroll
        for (int j = 0; j < 8; j++) acc[i][j] = 0.f;

    for (int k0 = 0; k0 < K; k0 += 8) {
        float4 a = *(const float4*)&Ab[(size_t)rowA * K + k0 + colA];
        As[colA+0][rowA] = a.x;
        As[colA+1][rowA] = a.y;
        As[colA+2][rowA] = a.z;
        As[colA+3][rowA] = a.w;
        *(float4*)&Bs[rowB][colB] =
            *(const float4*)&Bbp[(size_t)(k0 + rowB) * N + colB];
        __syncthreads();

        #pragma unroll
        for (int k = 0; k < 8; k++) {
            float rm[8], rn[8];
            *(float4*)&rm[0] = *(float4*)&As[k][tr*8];
            *(float4*)&rm[4] = *(float4*)&As[k][tr*8+4];
            *(float4*)&rn[0] = *(float4*)&Bs[k][tc*8];
            *(float4*)&rn[4] = *(float4*)&Bs[k][tc*8+4];
            #pragma unroll
            for (int i = 0; i < 8; i++)
                #pragma unroll
                for (int j = 0; j < 8; j++)
                    acc[i][j] = fmaf(rm[i], rn[j], acc[i][j]);
        }
        __syncthreads();
    }

    #pragma unroll
    for (int i = 0; i < 8; i++) {
        const int m = cRow*128 + tr*8 + i;
        #pragma unroll
        for (int j = 0; j < 8; j += 4) {
            const int n = cCol*128 + tc*8 + j;
            float4 o;
            o.x = acc[i][j+0] + bo[n+0];
            o.y = acc[i][j+1] + bo[n+1];
            o.z = acc[i][j+2] + bo[n+2];
            o.w = acc[i][j+3] + bo[n+3];
            *(float4*)&out[(size_t)m * N + n] = o;
        }
    }
}

// ---------------------------------------------------------------------------
extern "C" void kernel_launch(void* const* d_in, const int* in_sizes, int n_in,
                              void* d_out, int out_size)
{
    const float* x     = (const float*)d_in[0];
    const float* W_qkv = (const float*)d_in[1];
    const float* b_qkv = (const float*)d_in[2];
    const float* W_out = (const float*)d_in[3];
    const float* b_out = (const float*)d_in[4];
    float* out = (float*)d_out;

    cudaFuncSetAttribute(attn_kernel,
        cudaFuncAttributeMaxDynamicSharedMemorySize, ATTN_SMEM);

    dim3 g1(NQKV_/128, Mm_/128);          // (24, 32)
    qkv_gemm_kernel<<<g1, 256>>>(x, W_qkv, b_qkv);

    dim3 g2(Ss_/64, Bb_*Hh_);             // (32, 32)
    attn_kernel<<<g2, 256, ATTN_SMEM>>>();

    dim3 g3(Dd_/128, Mm_/128);            // (8, 32)
    out_gemm_kernel<<<g3, 256>>>(W_out, b_out, out);
}